// round 5
// baseline (speedup 1.0000x reference)
#include <cuda_runtime.h>
#include <math.h>

#define DIMX 1024
#define NPROJ 5120
#define ROWS 8192
#define LSEQ 2048
#define HD 128

// Scratch (device-global: allocation-free per harness rules)
__device__ float g_h[(size_t)ROWS * DIMX];        //  32 MB  LayerNorm output
__device__ float g_proj[(size_t)ROWS * NPROJ];    // 160 MB  QKV/lin/pre projections
__device__ float g_branch[(size_t)ROWS * 2048];   //  64 MB  [gelu-gate | attn]

typedef unsigned long long ull;

// ---- packed f32x2 helpers (Blackwell FFMA2 path; IEEE fp32 per lane) ----
__device__ __forceinline__ ull pk2(float lo, float hi) {
    ull r; asm("mov.b64 %0, {%1, %2};" : "=l"(r) : "f"(lo), "f"(hi)); return r;
}
__device__ __forceinline__ void up2(ull v, float& lo, float& hi) {
    asm("mov.b64 {%0, %1}, %2;" : "=f"(lo), "=f"(hi) : "l"(v));
}
__device__ __forceinline__ void fma2(ull& d, ull a, ull b) {
    asm("fma.rn.f32x2 %0, %1, %2, %3;" : "=l"(d) : "l"(a), "l"(b), "l"(d));
}
__device__ __forceinline__ ull mul2(ull a, ull b) {
    ull r; asm("mul.rn.f32x2 %0, %1, %2;" : "=l"(r) : "l"(a), "l"(b)); return r;
}

// ============================ LayerNorm ============================
__global__ void __launch_bounds__(256) ln_kernel(
        const float* __restrict__ x, const float* __restrict__ gamma,
        const float* __restrict__ beta, float* __restrict__ h) {
    int row = blockIdx.x;
    int t = threadIdx.x;
    float4 a = reinterpret_cast<const float4*>(x + (size_t)row * DIMX)[t];
    float s  = a.x + a.y + a.z + a.w;
    float ss = a.x * a.x + a.y * a.y + a.z * a.z + a.w * a.w;
    #pragma unroll
    for (int o = 16; o > 0; o >>= 1) {
        s  += __shfl_xor_sync(0xffffffffu, s, o);
        ss += __shfl_xor_sync(0xffffffffu, ss, o);
    }
    __shared__ float rs[8], rss[8];
    if ((t & 31) == 0) { rs[t >> 5] = s; rss[t >> 5] = ss; }
    __syncthreads();
    if (t < 32) {
        s  = (t < 8) ? rs[t]  : 0.f;
        ss = (t < 8) ? rss[t] : 0.f;
        #pragma unroll
        for (int o = 4; o > 0; o >>= 1) {
            s  += __shfl_xor_sync(0xffffffffu, s, o);
            ss += __shfl_xor_sync(0xffffffffu, ss, o);
        }
        if (t == 0) { rs[0] = s; rss[0] = ss; }
    }
    __syncthreads();
    float mu   = rs[0] * (1.0f / DIMX);
    float var  = rss[0] * (1.0f / DIMX) - mu * mu;
    float rstd = rsqrtf(var + 1e-5f);
    float4 g  = reinterpret_cast<const float4*>(gamma)[t];
    float4 be = reinterpret_cast<const float4*>(beta)[t];
    float4 o;
    o.x = (a.x - mu) * rstd * g.x + be.x;
    o.y = (a.y - mu) * rstd * g.y + be.y;
    o.z = (a.z - mu) * rstd * g.z + be.z;
    o.w = (a.w - mu) * rstd * g.w + be.w;
    reinterpret_cast<float4*>(h + (size_t)row * DIMX)[t] = o;
}

// ============================ SGEMM (C = A * B^T [+resid]) ============================
// A:[M,K] row-major, B:[N,K] row-major. 128x128x8 tile, 256 threads, 8x8 micro
// as 8 rows x 4 f32x2 column-pairs. Smem padded to 132 words (conflict-free).
#define BM 128
#define BN 128
#define BK 8
#define SW (BM + 4)

template<bool RES>
__global__ void __launch_bounds__(256) sgemm_nt(
        const float* __restrict__ A, const float* __restrict__ B,
        float* __restrict__ C, const float* __restrict__ resid,
        int M, int N, int K) {
    __shared__ float As[BK][SW];
    __shared__ float Bs[BK][SW];
    int t  = threadIdx.x;
    int tx = t & 15, ty = t >> 4;
    int row0 = blockIdx.y * BM;
    int col0 = blockIdx.x * BN;
    int lr = t >> 1;             // 0..127 (tile row/col for loading)
    int lk = (t & 1) * 4;        // k offset 0 or 4
    const float* Ag = A + (size_t)(row0 + lr) * K + lk;
    const float* Bg = B + (size_t)(col0 + lr) * K + lk;

    ull acc[8][4];
    #pragma unroll
    for (int i = 0; i < 8; i++)
        #pragma unroll
        for (int j = 0; j < 4; j++) acc[i][j] = 0ull;

    for (int k0 = 0; k0 < K; k0 += BK) {
        float4 av = *reinterpret_cast<const float4*>(Ag + k0);
        float4 bv = *reinterpret_cast<const float4*>(Bg + k0);
        As[lk + 0][lr] = av.x; As[lk + 1][lr] = av.y;
        As[lk + 2][lr] = av.z; As[lk + 3][lr] = av.w;
        Bs[lk + 0][lr] = bv.x; Bs[lk + 1][lr] = bv.y;
        Bs[lk + 2][lr] = bv.z; Bs[lk + 3][lr] = bv.w;
        __syncthreads();
        #pragma unroll
        for (int kk = 0; kk < BK; kk++) {
            float4 a0 = *reinterpret_cast<const float4*>(&As[kk][ty * 4]);
            float4 a1 = *reinterpret_cast<const float4*>(&As[kk][ty * 4 + 64]);
            ulonglong2 b0 = *reinterpret_cast<const ulonglong2*>(&Bs[kk][tx * 4]);
            ulonglong2 b1 = *reinterpret_cast<const ulonglong2*>(&Bs[kk][tx * 4 + 64]);
            float ar[8] = {a0.x, a0.y, a0.z, a0.w, a1.x, a1.y, a1.z, a1.w};
            ull bp[4] = {b0.x, b0.y, b1.x, b1.y};
            #pragma unroll
            for (int i = 0; i < 8; i++) {
                ull a2 = pk2(ar[i], ar[i]);
                fma2(acc[i][0], a2, bp[0]);
                fma2(acc[i][1], a2, bp[1]);
                fma2(acc[i][2], a2, bp[2]);
                fma2(acc[i][3], a2, bp[3]);
            }
        }
        __syncthreads();
    }

    #pragma unroll
    for (int i = 0; i < 8; i++) {
        int r = row0 + ty * 4 + (i & 3) + (i >> 2) * 64;
        #pragma unroll
        for (int half = 0; half < 2; half++) {
            int c = col0 + tx * 4 + half * 64;
            float4 o;
            up2(acc[i][half * 2 + 0], o.x, o.y);
            up2(acc[i][half * 2 + 1], o.z, o.w);
            if (RES) {
                float4 rv = *reinterpret_cast<const float4*>(resid + (size_t)r * N + c);
                o.x += rv.x; o.y += rv.y; o.z += rv.z; o.w += rv.w;
            }
            *reinterpret_cast<float4*>(C + (size_t)r * N + c) = o;
        }
    }
}

// ============================ GELU gate ============================
// branch[:, :1024] = lin * gelu_exact(pre)
__global__ void __launch_bounds__(256) gelu_kernel(
        const float* __restrict__ proj, float* __restrict__ branch) {
    int row = blockIdx.x;
    int t = threadIdx.x;
    float4 l4 = reinterpret_cast<const float4*>(proj + (size_t)row * NPROJ + 3 * DIMX)[t];
    float4 p4 = reinterpret_cast<const float4*>(proj + (size_t)row * NPROJ + 4 * DIMX)[t];
    const float inv_sqrt2 = 0.7071067811865475f;
    float4 o;
    o.x = l4.x * (0.5f * p4.x * (1.0f + erff(p4.x * inv_sqrt2)));
    o.y = l4.y * (0.5f * p4.y * (1.0f + erff(p4.y * inv_sqrt2)));
    o.z = l4.z * (0.5f * p4.z * (1.0f + erff(p4.z * inv_sqrt2)));
    o.w = l4.w * (0.5f * p4.w * (1.0f + erff(p4.w * inv_sqrt2)));
    reinterpret_cast<float4*>(branch + (size_t)row * 2048)[t] = o;
}

// ============================ Attention (flash, power-softmax p=2) ============================
// Per block: one (b,h,q-tile of 64). Running max m, Z = sum e^2 (e = exp(s-m)),
// out = U * Z^{-1/2}. 116 KB dynamic smem, strided-by-16 micro mapping.
#define AW 132
#define SSW 66

__global__ void __launch_bounds__(256, 1) attn_kernel(
        const float* __restrict__ proj, float* __restrict__ branch) {
    extern __shared__ float sm[];
    float* Qn   = sm;                  // [64][132]
    float* Kn   = Qn + 64 * AW;        // [64][132]
    float* Vn   = Kn + 64 * AW;        // [64][132]
    float* Ss   = Vn + 64 * AW;        // [64][66]
    float* mrow = Ss + 64 * SSW;       // [64]
    float* zrow = mrow + 64;           // [64]
    float* arow = zrow + 64;           // [64]

    int t = threadIdx.x, tx = t & 15, ty = t >> 4;
    int bh = blockIdx.y;
    int b = bh >> 3, h = bh & 7;
    int q0 = blockIdx.x * 64;
    const float* base = proj + (size_t)b * LSEQ * NPROJ + (size_t)h * HD;
    const float scale = 0.08838834764831845f;   // 128^-0.5

    // Load Q tile (coalesced; conflict-free STS.128)
    #pragma unroll
    for (int l = 0; l < 8; l++) {
        int idx = t + l * 256;
        int i = idx >> 5, dg = (idx & 31) * 4;
        float4 v = *reinterpret_cast<const float4*>(base + (size_t)(q0 + i) * NPROJ + dg);
        *reinterpret_cast<float4*>(&Qn[i * AW + dg]) = v;
    }
    if (t < 64) { mrow[t] = -1e30f; zrow[t] = 0.f; }

    ull u2[4][4];
    #pragma unroll
    for (int i = 0; i < 4; i++)
        #pragma unroll
        for (int j = 0; j < 4; j++) u2[i][j] = 0ull;

    for (int k0 = 0; k0 < q0 + 64; k0 += 64) {
        __syncthreads();   // previous PV done (and Q/m/z init on first iter)
        // Load K and V tiles
        #pragma unroll
        for (int l = 0; l < 8; l++) {
            int idx = t + l * 256;
            int i = idx >> 5, dg = (idx & 31) * 4;
            const float* kp = base + DIMX + (size_t)(k0 + i) * NPROJ + dg;
            *reinterpret_cast<float4*>(&Kn[i * AW + dg]) = *reinterpret_cast<const float4*>(kp);
            *reinterpret_cast<float4*>(&Vn[i * AW + dg]) = *reinterpret_cast<const float4*>(kp + DIMX);
        }
        __syncthreads();

        // S = Q K^T : 4x4 micro, d-paired f32x2 (acc holds even/odd-d partials)
        ull s2[4][4];
        #pragma unroll
        for (int i = 0; i < 4; i++)
            #pragma unroll
            for (int j = 0; j < 4; j++) s2[i][j] = 0ull;
        #pragma unroll 4
        for (int d = 0; d < HD; d += 4) {
            ulonglong2 qa[4], kb[4];
            #pragma unroll
            for (int i = 0; i < 4; i++)
                qa[i] = *reinterpret_cast<const ulonglong2*>(&Qn[(ty + 16 * i) * AW + d]);
            #pragma unroll
            for (int j = 0; j < 4; j++)
                kb[j] = *reinterpret_cast<const ulonglong2*>(&Kn[(tx + 16 * j) * AW + d]);
            #pragma unroll
            for (int i = 0; i < 4; i++)
                #pragma unroll
                for (int j = 0; j < 4; j++) {
                    fma2(s2[i][j], qa[i].x, kb[j].x);
                    fma2(s2[i][j], qa[i].y, kb[j].y);
                }
        }
        // scale + causal mask + write to Ss
        #pragma unroll
        for (int i = 0; i < 4; i++) {
            int qg = q0 + ty + 16 * i;
            #pragma unroll
            for (int j = 0; j < 4; j++) {
                float e, o_;
                up2(s2[i][j], e, o_);
                float s = (e + o_) * scale;
                int kg = k0 + tx + 16 * j;
                if (kg > qg) s = -1e30f;
                Ss[(ty + 16 * i) * SSW + (tx + 16 * j)] = s;
            }
        }
        __syncthreads();

        // per-row online power-softmax update (p=2): Z accumulates e^2
        if (t < 64) {
            float mo = mrow[t], mn = mo;
            float* srow = &Ss[t * SSW];
            #pragma unroll 8
            for (int c = 0; c < 64; c++) mn = fmaxf(mn, srow[c]);
            float zc = zrow[t] * expf(2.0f * (mo - mn));
            #pragma unroll 8
            for (int c = 0; c < 64; c++) {
                float e = expf(srow[c] - mn);
                srow[c] = e;
                zc += e * e;
            }
            arow[t] = expf(mo - mn);
            mrow[t] = mn;
            zrow[t] = zc;
        }
        __syncthreads();

        // rescale U, then U += P * V  (4 rows x 8 cols per thread, f32x2 col-pairs)
        #pragma unroll
        for (int i = 0; i < 4; i++) {
            float al = arow[ty + 16 * i];
            ull al2 = pk2(al, al);
            #pragma unroll
            for (int j = 0; j < 4; j++) u2[i][j] = mul2(u2[i][j], al2);
        }
        #pragma unroll 4
        for (int kk = 0; kk < 64; kk++) {
            float p[4];
            #pragma unroll
            for (int i = 0; i < 4; i++) p[i] = Ss[(ty + 16 * i) * SSW + kk];
            ulonglong2 v0 = *reinterpret_cast<const ulonglong2*>(&Vn[kk * AW + tx * 4]);
            ulonglong2 v1 = *reinterpret_cast<const ulonglong2*>(&Vn[kk * AW + tx * 4 + 64]);
            ull vv[4] = {v0.x, v0.y, v1.x, v1.y};
            #pragma unroll
            for (int i = 0; i < 4; i++) {
                ull p2 = pk2(p[i], p[i]);
                fma2(u2[i][0], p2, vv[0]);
                fma2(u2[i][1], p2, vv[1]);
                fma2(u2[i][2], p2, vv[2]);
                fma2(u2[i][3], p2, vv[3]);
            }
        }
    }

    // O = U * Z^{-1/2} -> branch[:, 1024 + h*128 + ...]
    #pragma unroll
    for (int i = 0; i < 4; i++) {
        int qg = q0 + ty + 16 * i;
        float rz = rsqrtf(zrow[ty + 16 * i]);
        float* out = branch + (size_t)(b * LSEQ + qg) * 2048 + 1024 + h * HD;
        #pragma unroll
        for (int half = 0; half < 2; half++) {
            float4 o;
            up2(u2[i][half * 2 + 0], o.x, o.y);
            up2(u2[i][half * 2 + 1], o.z, o.w);
            o.x *= rz; o.y *= rz; o.z *= rz; o.w *= rz;
            *reinterpret_cast<float4*>(out + tx * 4 + half * 64) = o;
        }
    }
}

// ============================ launch ============================
extern "C" void kernel_launch(void* const* d_in, const int* in_sizes, int n_in,
                              void* d_out, int out_size) {
    (void)in_sizes; (void)n_in; (void)out_size;
    const float* x     = (const float*)d_in[0];
    const float* gamma = (const float*)d_in[1];
    const float* beta  = (const float*)d_in[2];
    const float* w_qkv = (const float*)d_in[3];
    const float* w_out = (const float*)d_in[4];
    float* out = (float*)d_out;

    void *ph, *pp, *pb;
    cudaGetSymbolAddress(&ph, g_h);
    cudaGetSymbolAddress(&pp, g_proj);
    cudaGetSymbolAddress(&pb, g_branch);
    float* h      = (float*)ph;
    float* proj   = (float*)pp;
    float* branch = (float*)pb;

    // 1. LayerNorm
    ln_kernel<<<ROWS, 256>>>(x, gamma, beta, h);
    // 2. proj = h @ w_qkv^T   [8192 x 5120]
    sgemm_nt<false><<<dim3(NPROJ / BN, ROWS / BM), 256>>>(h, w_qkv, proj, nullptr,
                                                          ROWS, NPROJ, DIMX);
    // 3. branch[:, :1024] = lin * gelu(pre)
    gelu_kernel<<<ROWS, 256>>>(proj, branch);
    // 4. branch[:, 1024:] = attention(q, k, v)
    int smem = (3 * 64 * AW + 64 * SSW + 3 * 64) * (int)sizeof(float);
    cudaFuncSetAttribute(attn_kernel, cudaFuncAttributeMaxDynamicSharedMemorySize, smem);
    attn_kernel<<<dim3(LSEQ / 64, 32), 256, smem>>>(proj, branch);
    // 5. out = x + branch @ w_out^T   [8192 x 1024]
    sgemm_nt<true><<<dim3(DIMX / BN, ROWS / BM), 256>>>(branch, w_out, out, x,
                                                        ROWS, DIMX, 2048);
}

// round 14
// speedup vs baseline: 1.3896x; 1.3896x over previous
#include <cuda_runtime.h>
#include <cuda_bf16.h>
#include <math.h>
#include <stdint.h>

#define DIMX 1024
#define NPROJ 5120
#define ROWS 8192
#define LSEQ 2048
#define HD 128

typedef unsigned long long ull;
typedef __nv_bfloat16 bf16;

// ---------------- scratch (device globals: allocation-free) ----------------
__device__ float g_proj[(size_t)ROWS * NPROJ];        // 160 MB fp32
__device__ bf16  g_h0[(size_t)ROWS * DIMX];           // LN out hi plane
__device__ bf16  g_h1[(size_t)ROWS * DIMX];           // LN out lo plane
__device__ bf16  g_wq0[(size_t)NPROJ * DIMX];
__device__ bf16  g_wq1[(size_t)NPROJ * DIMX];
__device__ bf16  g_br0[(size_t)ROWS * 2048];
__device__ bf16  g_br1[(size_t)ROWS * 2048];
__device__ bf16  g_wo0[(size_t)DIMX * 2048];
__device__ bf16  g_wo1[(size_t)DIMX * 2048];

// ---------------- f32x2 helpers (attention path) ----------------
__device__ __forceinline__ ull pk2(float lo, float hi) {
    ull r; asm("mov.b64 %0, {%1, %2};" : "=l"(r) : "f"(lo), "f"(hi)); return r;
}
__device__ __forceinline__ void up2(ull v, float& lo, float& hi) {
    asm("mov.b64 {%0, %1}, %2;" : "=f"(lo), "=f"(hi) : "l"(v));
}
__device__ __forceinline__ void fma2(ull& d, ull a, ull b) {
    asm("fma.rn.f32x2 %0, %1, %2, %3;" : "=l"(d) : "l"(a), "l"(b), "l"(d));
}
__device__ __forceinline__ ull mul2(ull a, ull b) {
    ull r; asm("mul.rn.f32x2 %0, %1, %2;" : "=l"(r) : "l"(a), "l"(b)); return r;
}

// ---------------- bf16 split + pack ----------------
__device__ __forceinline__ void bfsplit(float v, bf16& h, bf16& l) {
    h = __float2bfloat16(v);
    l = __float2bfloat16(v - __bfloat162float(h));
}
__device__ __forceinline__ ull bpack4(bf16 a, bf16 b, bf16 c, bf16 d) {
    unsigned lo = ((unsigned)__bfloat16_as_ushort(b) << 16) | __bfloat16_as_ushort(a);
    unsigned hi = ((unsigned)__bfloat16_as_ushort(d) << 16) | __bfloat16_as_ushort(c);
    return ((ull)hi << 32) | lo;
}
// split a float4 into packed hi/lo 4-element bf16 words
__device__ __forceinline__ void split4(float4 v, ull& ph, ull& pl) {
    bf16 hx, lx, hy, ly, hz, lz, hw, lw;
    bfsplit(v.x, hx, lx); bfsplit(v.y, hy, ly);
    bfsplit(v.z, hz, lz); bfsplit(v.w, hw, lw);
    ph = bpack4(hx, hy, hz, hw);
    pl = bpack4(lx, ly, lz, lw);
}

__device__ __forceinline__ uint32_t smem_u32(const void* p) {
    uint32_t a;
    asm("{ .reg .u64 t; cvta.to.shared.u64 t, %1; cvt.u32.u64 %0, t; }" : "=r"(a) : "l"(p));
    return a;
}

// ---------------- mma/ldmatrix/cp.async macros (baseline PTX, sm_80-class) ----------------
#define LDX4(r0, r1, r2, r3, addr)                                            \
    asm volatile("ldmatrix.sync.aligned.m8n8.x4.shared.b16 {%0,%1,%2,%3}, [%4];" \
        : "=r"(r0), "=r"(r1), "=r"(r2), "=r"(r3) : "r"(addr))
#define MMA_BF16(c, a, b0, b1)                                                \
    asm volatile("mma.sync.aligned.m16n8k16.row.col.f32.bf16.bf16.f32 "       \
        "{%0,%1,%2,%3}, {%4,%5,%6,%7}, {%8,%9}, {%0,%1,%2,%3};"               \
        : "+f"((c)[0]), "+f"((c)[1]), "+f"((c)[2]), "+f"((c)[3])              \
        : "r"((a)[0]), "r"((a)[1]), "r"((a)[2]), "r"((a)[3]), "r"(b0), "r"(b1))
#define CP16(s, g)                                                            \
    asm volatile("cp.async.ca.shared.global [%0], [%1], 16;" :: "r"(s), "l"(g) : "memory")
#define CP_COMMIT asm volatile("cp.async.commit_group;" ::: "memory")
#define CP_WAIT1 asm volatile("cp.async.wait_group 1;" ::: "memory")
#define CP_WAIT0 asm volatile("cp.async.wait_group 0;" ::: "memory")

// ---------------- weight split prepass ----------------
__global__ void __launch_bounds__(256) split_kernel(const float* __restrict__ src,
                                                    bf16* __restrict__ hi,
                                                    bf16* __restrict__ lo, int n4) {
    int i = blockIdx.x * 256 + threadIdx.x;
    if (i >= n4) return;
    float4 v = reinterpret_cast<const float4*>(src)[i];
    ull ph, pl;
    split4(v, ph, pl);
    reinterpret_cast<ull*>(hi)[i] = ph;
    reinterpret_cast<ull*>(lo)[i] = pl;
}

// ---------------- LayerNorm (emits bf16 hi/lo planes) ----------------
__global__ void __launch_bounds__(256) ln_kernel(
        const float* __restrict__ x, const float* __restrict__ gamma,
        const float* __restrict__ beta, bf16* __restrict__ h0, bf16* __restrict__ h1) {
    int row = blockIdx.x;
    int t = threadIdx.x;
    float4 a = reinterpret_cast<const float4*>(x + (size_t)row * DIMX)[t];
    float s  = a.x + a.y + a.z + a.w;
    float ss = a.x * a.x + a.y * a.y + a.z * a.z + a.w * a.w;
    #pragma unroll
    for (int o = 16; o > 0; o >>= 1) {
        s  += __shfl_xor_sync(0xffffffffu, s, o);
        ss += __shfl_xor_sync(0xffffffffu, ss, o);
    }
    __shared__ float rs[8], rss[8];
    if ((t & 31) == 0) { rs[t >> 5] = s; rss[t >> 5] = ss; }
    __syncthreads();
    if (t < 32) {
        s  = (t < 8) ? rs[t]  : 0.f;
        ss = (t < 8) ? rss[t] : 0.f;
        #pragma unroll
        for (int o = 4; o > 0; o >>= 1) {
            s  += __shfl_xor_sync(0xffffffffu, s, o);
            ss += __shfl_xor_sync(0xffffffffu, ss, o);
        }
        if (t == 0) { rs[0] = s; rss[0] = ss; }
    }
    __syncthreads();
    float mu   = rs[0] * (1.0f / DIMX);
    float var  = rss[0] * (1.0f / DIMX) - mu * mu;
    float rstd = rsqrtf(var + 1e-5f);
    float4 g  = reinterpret_cast<const float4*>(gamma)[t];
    float4 be = reinterpret_cast<const float4*>(beta)[t];
    float4 o;
    o.x = (a.x - mu) * rstd * g.x + be.x;
    o.y = (a.y - mu) * rstd * g.y + be.y;
    o.z = (a.z - mu) * rstd * g.z + be.z;
    o.w = (a.w - mu) * rstd * g.w + be.w;
    ull ph, pl;
    split4(o, ph, pl);
    reinterpret_cast<ull*>(h0 + (size_t)row * DIMX)[t] = ph;
    reinterpret_cast<ull*>(h1 + (size_t)row * DIMX)[t] = pl;
}

// ---------------- bf16 3-term GEMM: C = A*B^T [+resid] ----------------
// A:[M,K], B:[N,K] row-major, each as hi/lo bf16 planes. 3 K-segments:
// (A0,B0), (A0,B1), (A1,B0) -> fp32-accurate to ~2^-18.
// Tile 128x128x32; 8 warps as 4(M)x2(N), 32x64 per warp; cp.async double buffer.
#define SROW 40                   // bf16 per smem row (80 B, conflict-free for ldmatrix)
#define BUFB (128 * SROW * 2)     // bytes per matrix per buffer

template<bool RES>
__global__ void __launch_bounds__(256, 2) gemm_bf16_kernel(
        const bf16* __restrict__ A0, const bf16* __restrict__ A1,
        const bf16* __restrict__ B0, const bf16* __restrict__ B1,
        float* __restrict__ C, const float* __restrict__ resid,
        int K, int kcLog, int Ntot) {
    __shared__ bf16 As[2][128 * SROW];
    __shared__ bf16 Bs[2][128 * SROW];
    int tid = threadIdx.x;
    int lane = tid & 31, wid = tid >> 5;
    int wm = wid >> 1, wn = wid & 1;
    int row0 = blockIdx.y * 128;
    int col0 = blockIdx.x * 128;
    uint32_t sA = smem_u32(As);
    uint32_t sB = smem_u32(Bs);

    const int kcMask = (1 << kcLog) - 1;
    const int NCk = 3 << kcLog;

    // loader thread mapping: 2 threads per row, 32 B each
    int lr = tid >> 1;
    int ls2 = (tid & 1) * 2;            // 16B-segment pair {0,1} or {2,3}
    uint32_t sOffA = (uint32_t)(lr * SROW + ls2 * 8) * 2;

    // ldmatrix lane addresses (buffer 0 base)
    uint32_t aAdr[2][2];
    #pragma unroll
    for (int mi = 0; mi < 2; mi++)
        #pragma unroll
        for (int kk = 0; kk < 2; kk++)
            aAdr[mi][kk] = sA + (uint32_t)((wm * 32 + mi * 16 + (lane & 15)) * SROW
                                           + kk * 16 + (lane >> 4) * 8) * 2;
    uint32_t bAdr = sB + (uint32_t)((wn * 64 + (lane & 7)) * SROW + (lane >> 3) * 8) * 2;

    float acc[2][8][4];
    #pragma unroll
    for (int mi = 0; mi < 2; mi++)
        #pragma unroll
        for (int nb = 0; nb < 8; nb++)
            #pragma unroll
            for (int q = 0; q < 4; q++) acc[mi][nb][q] = 0.f;

    // ---- prefetch chunk 0 ----
    {
        const bf16* ga = A0 + (size_t)(row0 + lr) * K + ls2 * 8;
        const bf16* gb = B0 + (size_t)(col0 + lr) * K + ls2 * 8;
        CP16(sA + sOffA, ga); CP16(sA + sOffA + 16, ga + 8);
        CP16(sB + sOffA, gb); CP16(sB + sOffA + 16, gb + 8);
        CP_COMMIT;
    }

    for (int c = 0; c < NCk; c++) {
        int buf = c & 1;
        if (c + 1 < NCk) {
            int cn = c + 1;
            int seg = cn >> kcLog, kc = cn & kcMask;
            const bf16* Ap = (seg == 2) ? A1 : A0;
            const bf16* Bp = (seg == 1) ? B1 : B0;
            uint32_t bo = (uint32_t)(buf ^ 1) * BUFB;
            const bf16* ga = Ap + (size_t)(row0 + lr) * K + (kc << 5) + ls2 * 8;
            const bf16* gb = Bp + (size_t)(col0 + lr) * K + (kc << 5) + ls2 * 8;
            CP16(sA + bo + sOffA, ga); CP16(sA + bo + sOffA + 16, ga + 8);
            CP16(sB + bo + sOffA, gb); CP16(sB + bo + sOffA + 16, gb + 8);
            CP_COMMIT;
            CP_WAIT1;
        } else {
            CP_WAIT0;
        }
        __syncthreads();

        uint32_t bo = (uint32_t)buf * BUFB;
        uint32_t a[2][2][4];
        #pragma unroll
        for (int mi = 0; mi < 2; mi++)
            #pragma unroll
            for (int kk = 0; kk < 2; kk++)
                LDX4(a[mi][kk][0], a[mi][kk][1], a[mi][kk][2], a[mi][kk][3],
                     aAdr[mi][kk] + bo);
        #pragma unroll
        for (int nb = 0; nb < 8; nb++) {
            uint32_t q0, q1, q2, q3;
            LDX4(q0, q1, q2, q3, bAdr + bo + (uint32_t)nb * (8 * SROW * 2));
            #pragma unroll
            for (int mi = 0; mi < 2; mi++) {
                MMA_BF16(acc[mi][nb], a[mi][0], q0, q1);
                MMA_BF16(acc[mi][nb], a[mi][1], q2, q3);
            }
        }
        __syncthreads();
    }

    // epilogue
    int gid = lane >> 2, tg = lane & 3;
    #pragma unroll
    for (int mi = 0; mi < 2; mi++) {
        #pragma unroll
        for (int nb = 0; nb < 8; nb++) {
            int r = row0 + wm * 32 + mi * 16 + gid;
            int col = col0 + wn * 64 + nb * 8 + tg * 2;
            float2 v0 = make_float2(acc[mi][nb][0], acc[mi][nb][1]);
            float2 v1 = make_float2(acc[mi][nb][2], acc[mi][nb][3]);
            if (RES) {
                float2 r0 = *reinterpret_cast<const float2*>(resid + (size_t)r * Ntot + col);
                float2 r1 = *reinterpret_cast<const float2*>(resid + (size_t)(r + 8) * Ntot + col);
                v0.x += r0.x; v0.y += r0.y; v1.x += r1.x; v1.y += r1.y;
            }
            *reinterpret_cast<float2*>(C + (size_t)r * Ntot + col) = v0;
            *reinterpret_cast<float2*>(C + (size_t)(r + 8) * Ntot + col) = v1;
        }
    }
}

// ---------------- GELU gate (emits branch hi/lo planes cols [0,1024)) ----------------
__global__ void __launch_bounds__(256) gelu_kernel(
        const float* __restrict__ proj, bf16* __restrict__ b0, bf16* __restrict__ b1) {
    int row = blockIdx.x;
    int t = threadIdx.x;
    float4 l4 = reinterpret_cast<const float4*>(proj + (size_t)row * NPROJ + 3 * DIMX)[t];
    float4 p4 = reinterpret_cast<const float4*>(proj + (size_t)row * NPROJ + 4 * DIMX)[t];
    const float is2 = 0.7071067811865475f;
    float4 o;
    o.x = l4.x * (0.5f * p4.x * (1.0f + erff(p4.x * is2)));
    o.y = l4.y * (0.5f * p4.y * (1.0f + erff(p4.y * is2)));
    o.z = l4.z * (0.5f * p4.z * (1.0f + erff(p4.z * is2)));
    o.w = l4.w * (0.5f * p4.w * (1.0f + erff(p4.w * is2)));
    ull ph, pl;
    split4(o, ph, pl);
    reinterpret_cast<ull*>(b0 + (size_t)row * 2048)[t] = ph;
    reinterpret_cast<ull*>(b1 + (size_t)row * 2048)[t] = pl;
}

// ---------------- Attention (flash, p=2 power-softmax) ----------------
#define AW 132
#define SSW 66

extern __shared__ float smf[];

__global__ void __launch_bounds__(256, 1) attn_kernel(
        const float* __restrict__ proj, bf16* __restrict__ bo0, bf16* __restrict__ bo1) {
    float* Qn   = smf;
    float* Kn   = Qn + 64 * AW;
    float* Vn   = Kn + 64 * AW;
    float* Ss   = Vn + 64 * AW;
    float* mrow = Ss + 64 * SSW;
    float* zrow = mrow + 64;
    float* arow = zrow + 64;

    int t = threadIdx.x, tx = t & 15, ty = t >> 4;
    int bh = blockIdx.y;
    int b = bh >> 3, h = bh & 7;
    int q0 = blockIdx.x * 64;
    const float* base = proj + (size_t)b * LSEQ * NPROJ + (size_t)h * HD;
    const float scale = 0.08838834764831845f;

    #pragma unroll
    for (int l = 0; l < 8; l++) {
        int idx = t + l * 256;
        int i = idx >> 5, dg = (idx & 31) * 4;
        float4 v = *reinterpret_cast<const float4*>(base + (size_t)(q0 + i) * NPROJ + dg);
        *reinterpret_cast<float4*>(&Qn[i * AW + dg]) = v;
    }
    if (t < 64) { mrow[t] = -1e30f; zrow[t] = 0.f; }

    ull u2[4][4];
    #pragma unroll
    for (int i = 0; i < 4; i++)
        #pragma unroll
        for (int j = 0; j < 4; j++) u2[i][j] = 0ull;

    for (int k0 = 0; k0 < q0 + 64; k0 += 64) {
        __syncthreads();
        #pragma unroll
        for (int l = 0; l < 8; l++) {
            int idx = t + l * 256;
            int i = idx >> 5, dg = (idx & 31) * 4;
            const float* kp = base + DIMX + (size_t)(k0 + i) * NPROJ + dg;
            *reinterpret_cast<float4*>(&Kn[i * AW + dg]) = *reinterpret_cast<const float4*>(kp);
            *reinterpret_cast<float4*>(&Vn[i * AW + dg]) = *reinterpret_cast<const float4*>(kp + DIMX);
        }
        __syncthreads();

        ull s2[4][4];
        #pragma unroll
        for (int i = 0; i < 4; i++)
            #pragma unroll
            for (int j = 0; j < 4; j++) s2[i][j] = 0ull;
        #pragma unroll 4
        for (int d = 0; d < HD; d += 4) {
            ulonglong2 qa[4], kb[4];
            #pragma unroll
            for (int i = 0; i < 4; i++)
                qa[i] = *reinterpret_cast<const ulonglong2*>(&Qn[(ty + 16 * i) * AW + d]);
            #pragma unroll
            for (int j = 0; j < 4; j++)
                kb[j] = *reinterpret_cast<const ulonglong2*>(&Kn[(tx + 16 * j) * AW + d]);
            #pragma unroll
            for (int i = 0; i < 4; i++)
                #pragma unroll
                for (int j = 0; j < 4; j++) {
                    fma2(s2[i][j], qa[i].x, kb[j].x);
                    fma2(s2[i][j], qa[i].y, kb[j].y);
                }
        }
        #pragma unroll
        for (int i = 0; i < 4; i++) {
            int qg = q0 + ty + 16 * i;
            #pragma unroll
            for (int j = 0; j < 4; j++) {
                float e, o_;
                up2(s2[i][j], e, o_);
                float s = (e + o_) * scale;
                int kg = k0 + tx + 16 * j;
                if (kg > qg) s = -1e30f;
                Ss[(ty + 16 * i) * SSW + (tx + 16 * j)] = s;
            }
        }
        __syncthreads();

        if (t < 64) {
            float mo = mrow[t], mn = mo;
            float* srow = &Ss[t * SSW];
            #pragma unroll 8
            for (int c = 0; c < 64; c++) mn = fmaxf(mn, srow[c]);
            float zc = zrow[t] * expf(2.0f * (mo - mn));
            #pragma unroll 8
            for (int c = 0; c < 64; c++) {
                float e = expf(srow[c] - mn);
                srow[c] = e;
                zc += e * e;
            }
            arow[t] = expf(mo - mn);
            mrow[t] = mn;
            zrow[t] = zc;
        }
        __syncthreads();

        #pragma unroll
        for (int i = 0; i < 4; i++) {
            float al = arow[ty + 16 * i];
            ull al2 = pk2(al, al);
            #pragma unroll
            for (int j = 0; j < 4; j++) u2[i][j] = mul2(u2[i][j], al2);
        }
        #pragma unroll 4
        for (int kk = 0; kk < 64; kk++) {
            float p[4];
            #pragma unroll
            for (int i = 0; i < 4; i++) p[i] = Ss[(ty + 16 * i) * SSW + kk];
            ulonglong2 v0 = *reinterpret_cast<const ulonglong2*>(&Vn[kk * AW + tx * 4]);
            ulonglong2 v1 = *reinterpret_cast<const ulonglong2*>(&Vn[kk * AW + tx * 4 + 64]);
            ull vv[4] = {v0.x, v0.y, v1.x, v1.y};
            #pragma unroll
            for (int i = 0; i < 4; i++) {
                ull p2 = pk2(p[i], p[i]);
                fma2(u2[i][0], p2, vv[0]);
                fma2(u2[i][1], p2, vv[1]);
                fma2(u2[i][2], p2, vv[2]);
                fma2(u2[i][3], p2, vv[3]);
            }
        }
    }

    #pragma unroll
    for (int i = 0; i < 4; i++) {
        int qg = q0 + ty + 16 * i;
        float rz = rsqrtf(zrow[ty + 16 * i]);
        size_t ob = (size_t)(b * LSEQ + qg) * 2048 + 1024 + h * HD;
        #pragma unroll
        for (int half = 0; half < 2; half++) {
            float4 o;
            up2(u2[i][half * 2 + 0], o.x, o.y);
            up2(u2[i][half * 2 + 1], o.z, o.w);
            o.x *= rz; o.y *= rz; o.z *= rz; o.w *= rz;
            ull ph, pl;
            split4(o, ph, pl);
            size_t off = ob + tx * 4 + half * 64;
            *reinterpret_cast<ull*>(bo0 + off) = ph;
            *reinterpret_cast<ull*>(bo1 + off) = pl;
        }
    }
}

// ---------------- launch ----------------
extern "C" void kernel_launch(void* const* d_in, const int* in_sizes, int n_in,
                              void* d_out, int out_size) {
    (void)in_sizes; (void)n_in; (void)out_size;
    const float* x     = (const float*)d_in[0];
    const float* gamma = (const float*)d_in[1];
    const float* beta  = (const float*)d_in[2];
    const float* w_qkv = (const float*)d_in[3];
    const float* w_out = (const float*)d_in[4];
    float* out = (float*)d_out;

    void *pp, *ph0, *ph1, *pq0, *pq1, *pb0, *pb1, *po0, *po1;
    cudaGetSymbolAddress(&pp,  g_proj);
    cudaGetSymbolAddress(&ph0, g_h0);  cudaGetSymbolAddress(&ph1, g_h1);
    cudaGetSymbolAddress(&pq0, g_wq0); cudaGetSymbolAddress(&pq1, g_wq1);
    cudaGetSymbolAddress(&pb0, g_br0); cudaGetSymbolAddress(&pb1, g_br1);
    cudaGetSymbolAddress(&po0, g_wo0); cudaGetSymbolAddress(&po1, g_wo1);
    float* proj = (float*)pp;
    bf16 *h0 = (bf16*)ph0, *h1 = (bf16*)ph1;
    bf16 *q0 = (bf16*)pq0, *q1 = (bf16*)pq1;
    bf16 *b0 = (bf16*)pb0, *b1 = (bf16*)pb1;
    bf16 *o0 = (bf16*)po0, *o1 = (bf16*)po1;

    // weight split prepass (bf16 hi/lo planes)
    int nq4 = NPROJ * DIMX / 4, no4 = DIMX * 2048 / 4;
    split_kernel<<<(nq4 + 255) / 256, 256>>>(w_qkv, q0, q1, nq4);
    split_kernel<<<(no4 + 255) / 256, 256>>>(w_out, o0, o1, no4);

    // LayerNorm -> h hi/lo
    ln_kernel<<<ROWS, 256>>>(x, gamma, beta, h0, h1);

    // GEMM1: proj = h @ w_qkv^T   (bf16 3-term mma.sync, K=1024 -> kcLog=5)
    gemm_bf16_kernel<false><<<dim3(NPROJ / 128, ROWS / 128), 256>>>(
        h0, h1, q0, q1, proj, nullptr, DIMX, 5, NPROJ);

    // GELU gate -> branch planes cols [0,1024)
    gelu_kernel<<<ROWS, 256>>>(proj, b0, b1);

    // attention -> branch planes cols [1024,2048)
    int asmem = (3 * 64 * AW + 64 * SSW + 3 * 64) * (int)sizeof(float);
    cudaFuncSetAttribute(attn_kernel, cudaFuncAttributeMaxDynamicSharedMemorySize, asmem);
    attn_kernel<<<dim3(LSEQ / 64, 32), 256, asmem>>>(proj, b0, b1);

    // GEMM2: out = x + branch @ w_out^T  (K=2048 -> kcLog=6, fused residual)
    gemm_bf16_kernel<true><<<dim3(DIMX / 128, ROWS / 128), 256>>>(
        b0, b1, o0, o1, out, x, 2048, 6, DIMX);
}

// round 15
// speedup vs baseline: 1.6255x; 1.1697x over previous
#include <cuda_runtime.h>
#include <cuda_bf16.h>
#include <math.h>
#include <stdint.h>

#define DIMX 1024
#define NPROJ 5120
#define ROWS 8192
#define LSEQ 2048
#define HD 128

typedef unsigned long long ull;
typedef __nv_bfloat16 bf16;

// ---------------- scratch (device globals: allocation-free) ----------------
__device__ float g_proj[(size_t)ROWS * NPROJ];        // 160 MB fp32
__device__ bf16  g_h0[(size_t)ROWS * DIMX];           // LN out hi plane
__device__ bf16  g_h1[(size_t)ROWS * DIMX];           // LN out lo plane
__device__ bf16  g_wq0[(size_t)NPROJ * DIMX];
__device__ bf16  g_wq1[(size_t)NPROJ * DIMX];
__device__ bf16  g_br0[(size_t)ROWS * 2048];
__device__ bf16  g_br1[(size_t)ROWS * 2048];
__device__ bf16  g_wo0[(size_t)DIMX * 2048];
__device__ bf16  g_wo1[(size_t)DIMX * 2048];

// ---------------- f32x2 helpers (attention path) ----------------
__device__ __forceinline__ ull pk2(float lo, float hi) {
    ull r; asm("mov.b64 %0, {%1, %2};" : "=l"(r) : "f"(lo), "f"(hi)); return r;
}
__device__ __forceinline__ void up2(ull v, float& lo, float& hi) {
    asm("mov.b64 {%0, %1}, %2;" : "=f"(lo), "=f"(hi) : "l"(v));
}
__device__ __forceinline__ void fma2(ull& d, ull a, ull b) {
    asm("fma.rn.f32x2 %0, %1, %2, %3;" : "=l"(d) : "l"(a), "l"(b), "l"(d));
}
__device__ __forceinline__ ull mul2(ull a, ull b) {
    ull r; asm("mul.rn.f32x2 %0, %1, %2;" : "=l"(r) : "l"(a), "l"(b)); return r;
}

// ---------------- bf16 split + pack ----------------
__device__ __forceinline__ void bfsplit(float v, bf16& h, bf16& l) {
    h = __float2bfloat16(v);
    l = __float2bfloat16(v - __bfloat162float(h));
}
__device__ __forceinline__ ull bpack4(bf16 a, bf16 b, bf16 c, bf16 d) {
    unsigned lo = ((unsigned)__bfloat16_as_ushort(b) << 16) | __bfloat16_as_ushort(a);
    unsigned hi = ((unsigned)__bfloat16_as_ushort(d) << 16) | __bfloat16_as_ushort(c);
    return ((ull)hi << 32) | lo;
}
__device__ __forceinline__ void split4(float4 v, ull& ph, ull& pl) {
    bf16 hx, lx, hy, ly, hz, lz, hw, lw;
    bfsplit(v.x, hx, lx); bfsplit(v.y, hy, ly);
    bfsplit(v.z, hz, lz); bfsplit(v.w, hw, lw);
    ph = bpack4(hx, hy, hz, hw);
    pl = bpack4(lx, ly, lz, lw);
}

__device__ __forceinline__ uint32_t smem_u32(const void* p) {
    uint32_t a;
    asm("{ .reg .u64 t; cvta.to.shared.u64 t, %1; cvt.u32.u64 %0, t; }" : "=r"(a) : "l"(p));
    return a;
}

// ---------------- mma/ldmatrix/cp.async macros (baseline PTX, sm_80-class) ----------------
#define LDX4(r0, r1, r2, r3, addr)                                            \
    asm volatile("ldmatrix.sync.aligned.m8n8.x4.shared.b16 {%0,%1,%2,%3}, [%4];" \
        : "=r"(r0), "=r"(r1), "=r"(r2), "=r"(r3) : "r"(addr))
#define LDX2(r0, r1, addr)                                                    \
    asm volatile("ldmatrix.sync.aligned.m8n8.x2.shared.b16 {%0,%1}, [%2];"    \
        : "=r"(r0), "=r"(r1) : "r"(addr))
#define MMA_BF16(c, a, b0, b1)                                                \
    asm volatile("mma.sync.aligned.m16n8k16.row.col.f32.bf16.bf16.f32 "       \
        "{%0,%1,%2,%3}, {%4,%5,%6,%7}, {%8,%9}, {%0,%1,%2,%3};"               \
        : "+f"((c)[0]), "+f"((c)[1]), "+f"((c)[2]), "+f"((c)[3])              \
        : "r"((a)[0]), "r"((a)[1]), "r"((a)[2]), "r"((a)[3]), "r"(b0), "r"(b1))
#define CP16(s, g)                                                            \
    asm volatile("cp.async.ca.shared.global [%0], [%1], 16;" :: "r"(s), "l"(g) : "memory")
#define CP_COMMIT asm volatile("cp.async.commit_group;" ::: "memory")
#define CP_WAIT1 asm volatile("cp.async.wait_group 1;" ::: "memory")
#define CP_WAIT0 asm volatile("cp.async.wait_group 0;" ::: "memory")

// ---------------- weight split prepass ----------------
__global__ void __launch_bounds__(256) split_kernel(const float* __restrict__ src,
                                                    bf16* __restrict__ hi,
                                                    bf16* __restrict__ lo, int n4) {
    int i = blockIdx.x * 256 + threadIdx.x;
    if (i >= n4) return;
    float4 v = reinterpret_cast<const float4*>(src)[i];
    ull ph, pl;
    split4(v, ph, pl);
    reinterpret_cast<ull*>(hi)[i] = ph;
    reinterpret_cast<ull*>(lo)[i] = pl;
}

// ---------------- LayerNorm (emits bf16 hi/lo planes) ----------------
__global__ void __launch_bounds__(256) ln_kernel(
        const float* __restrict__ x, const float* __restrict__ gamma,
        const float* __restrict__ beta, bf16* __restrict__ h0, bf16* __restrict__ h1) {
    int row = blockIdx.x;
    int t = threadIdx.x;
    float4 a = reinterpret_cast<const float4*>(x + (size_t)row * DIMX)[t];
    float s  = a.x + a.y + a.z + a.w;
    float ss = a.x * a.x + a.y * a.y + a.z * a.z + a.w * a.w;
    #pragma unroll
    for (int o = 16; o > 0; o >>= 1) {
        s  += __shfl_xor_sync(0xffffffffu, s, o);
        ss += __shfl_xor_sync(0xffffffffu, ss, o);
    }
    __shared__ float rs[8], rss[8];
    if ((t & 31) == 0) { rs[t >> 5] = s; rss[t >> 5] = ss; }
    __syncthreads();
    if (t < 32) {
        s  = (t < 8) ? rs[t]  : 0.f;
        ss = (t < 8) ? rss[t] : 0.f;
        #pragma unroll
        for (int o = 4; o > 0; o >>= 1) {
            s  += __shfl_xor_sync(0xffffffffu, s, o);
            ss += __shfl_xor_sync(0xffffffffu, ss, o);
        }
        if (t == 0) { rs[0] = s; rss[0] = ss; }
    }
    __syncthreads();
    float mu   = rs[0] * (1.0f / DIMX);
    float var  = rss[0] * (1.0f / DIMX) - mu * mu;
    float rstd = rsqrtf(var + 1e-5f);
    float4 g  = reinterpret_cast<const float4*>(gamma)[t];
    float4 be = reinterpret_cast<const float4*>(beta)[t];
    float4 o;
    o.x = (a.x - mu) * rstd * g.x + be.x;
    o.y = (a.y - mu) * rstd * g.y + be.y;
    o.z = (a.z - mu) * rstd * g.z + be.z;
    o.w = (a.w - mu) * rstd * g.w + be.w;
    ull ph, pl;
    split4(o, ph, pl);
    reinterpret_cast<ull*>(h0 + (size_t)row * DIMX)[t] = ph;
    reinterpret_cast<ull*>(h1 + (size_t)row * DIMX)[t] = pl;
}

// ---------------- bf16 3-term GEMM, fragment-reuse mainloop ----------------
// C = A*B^T [+resid]; A:[M,K], B:[N,K] row-major, hi/lo planes.
// Each k-chunk (32) visited ONCE: stage A0,A1,B0,B1; issue A0B0+A0B1+A1B0 with
// register-resident fragments (A0 reused by 2 terms, B0 by 2 terms).
// Tile 128x128x32; 8 warps 4(M)x2(N) -> 32x64/warp; cp.async double buffer.
#define SROW 40                    // bf16 per smem row (80 B, conflict-free)
#define PLANE (128 * SROW * 2)     // 10240 B per plane
#define GBUF (4 * PLANE)           // 40960 B per buffer (A0,A1,B0,B1)
#define GEMM_SMEM (2 * GBUF)       // 81920 B

extern __shared__ char smc[];

template<bool RES>
__global__ void __launch_bounds__(256, 2) gemm_bf16_kernel(
        const bf16* __restrict__ A0, const bf16* __restrict__ A1,
        const bf16* __restrict__ B0, const bf16* __restrict__ B1,
        float* __restrict__ C, const float* __restrict__ resid,
        int K, int Ntot) {
    uint32_t sbase = smem_u32(smc);
    int tid = threadIdx.x;
    int lane = tid & 31, wid = tid >> 5;
    int wm = wid >> 1, wn = wid & 1;
    int row0 = blockIdx.y * 128;
    int col0 = blockIdx.x * 128;

    const int NC = K >> 5;

    // loader mapping: 2 threads per row, 32 B each, per plane
    int lr = tid >> 1;
    int ls2 = (tid & 1) * 2;
    uint32_t sOff = (uint32_t)(lr * SROW + ls2 * 8) * 2;
    const bf16* gA0 = A0 + (size_t)(row0 + lr) * K + ls2 * 8;
    const bf16* gA1 = A1 + (size_t)(row0 + lr) * K + ls2 * 8;
    const bf16* gB0 = B0 + (size_t)(col0 + lr) * K + ls2 * 8;
    const bf16* gB1 = B1 + (size_t)(col0 + lr) * K + ls2 * 8;

    // ldmatrix offsets (plane-relative)
    uint32_t aOff[2][2];
    #pragma unroll
    for (int mi = 0; mi < 2; mi++)
        #pragma unroll
        for (int kk = 0; kk < 2; kk++)
            aOff[mi][kk] = (uint32_t)((wm * 32 + mi * 16 + (lane & 15)) * SROW
                                      + kk * 16 + (lane >> 4) * 8) * 2;
    uint32_t bOff = (uint32_t)((wn * 64 + (lane & 7)) * SROW + ((lane >> 3) & 1) * 8) * 2;

    float acc[2][8][4];
    #pragma unroll
    for (int mi = 0; mi < 2; mi++)
        #pragma unroll
        for (int nb = 0; nb < 8; nb++)
            #pragma unroll
            for (int q = 0; q < 4; q++) acc[mi][nb][q] = 0.f;

    auto load_chunk = [&](int c, int buf) {
        uint32_t bb = sbase + (uint32_t)buf * GBUF;
        int k0 = c << 5;
        const bf16* pa0 = gA0 + k0;
        const bf16* pa1 = gA1 + k0;
        const bf16* pb0 = gB0 + k0;
        const bf16* pb1 = gB1 + k0;
        CP16(bb + 0 * PLANE + sOff, pa0); CP16(bb + 0 * PLANE + sOff + 16, pa0 + 8);
        CP16(bb + 1 * PLANE + sOff, pa1); CP16(bb + 1 * PLANE + sOff + 16, pa1 + 8);
        CP16(bb + 2 * PLANE + sOff, pb0); CP16(bb + 2 * PLANE + sOff + 16, pb0 + 8);
        CP16(bb + 3 * PLANE + sOff, pb1); CP16(bb + 3 * PLANE + sOff + 16, pb1 + 8);
        CP_COMMIT;
    };

    load_chunk(0, 0);

    for (int c = 0; c < NC; c++) {
        int buf = c & 1;
        if (c + 1 < NC) { load_chunk(c + 1, buf ^ 1); CP_WAIT1; }
        else           { CP_WAIT0; }
        __syncthreads();

        uint32_t bb = sbase + (uint32_t)buf * GBUF;
        #pragma unroll
        for (int kk = 0; kk < 2; kk++) {
            uint32_t a0f[2][4], a1f[2][4];
            #pragma unroll
            for (int mi = 0; mi < 2; mi++) {
                LDX4(a0f[mi][0], a0f[mi][1], a0f[mi][2], a0f[mi][3],
                     bb + 0 * PLANE + aOff[mi][kk]);
                LDX4(a1f[mi][0], a1f[mi][1], a1f[mi][2], a1f[mi][3],
                     bb + 1 * PLANE + aOff[mi][kk]);
            }
            #pragma unroll
            for (int nb = 0; nb < 8; nb++) {
                uint32_t badd = bOff + (uint32_t)(nb * 8 * SROW + kk * 16) * 2;
                uint32_t q0, q1, r0, r1;
                LDX2(q0, q1, bb + 2 * PLANE + badd);   // B0 fragment
                LDX2(r0, r1, bb + 3 * PLANE + badd);   // B1 fragment
                #pragma unroll
                for (int mi = 0; mi < 2; mi++) {
                    MMA_BF16(acc[mi][nb], a0f[mi], q0, q1);   // A0*B0
                    MMA_BF16(acc[mi][nb], a0f[mi], r0, r1);   // A0*B1
                    MMA_BF16(acc[mi][nb], a1f[mi], q0, q1);   // A1*B0
                }
            }
        }
        __syncthreads();
    }

    // epilogue
    int gid = lane >> 2, tg = lane & 3;
    #pragma unroll
    for (int mi = 0; mi < 2; mi++) {
        #pragma unroll
        for (int nb = 0; nb < 8; nb++) {
            int r = row0 + wm * 32 + mi * 16 + gid;
            int col = col0 + wn * 64 + nb * 8 + tg * 2;
            float2 v0 = make_float2(acc[mi][nb][0], acc[mi][nb][1]);
            float2 v1 = make_float2(acc[mi][nb][2], acc[mi][nb][3]);
            if (RES) {
                float2 r0 = *reinterpret_cast<const float2*>(resid + (size_t)r * Ntot + col);
                float2 r1 = *reinterpret_cast<const float2*>(resid + (size_t)(r + 8) * Ntot + col);
                v0.x += r0.x; v0.y += r0.y; v1.x += r1.x; v1.y += r1.y;
            }
            *reinterpret_cast<float2*>(C + (size_t)r * Ntot + col) = v0;
            *reinterpret_cast<float2*>(C + (size_t)(r + 8) * Ntot + col) = v1;
        }
    }
}

// ---------------- GELU gate (emits branch hi/lo planes cols [0,1024)) ----------------
__global__ void __launch_bounds__(256) gelu_kernel(
        const float* __restrict__ proj, bf16* __restrict__ b0, bf16* __restrict__ b1) {
    int row = blockIdx.x;
    int t = threadIdx.x;
    float4 l4 = reinterpret_cast<const float4*>(proj + (size_t)row * NPROJ + 3 * DIMX)[t];
    float4 p4 = reinterpret_cast<const float4*>(proj + (size_t)row * NPROJ + 4 * DIMX)[t];
    const float is2 = 0.7071067811865475f;
    float4 o;
    o.x = l4.x * (0.5f * p4.x * (1.0f + erff(p4.x * is2)));
    o.y = l4.y * (0.5f * p4.y * (1.0f + erff(p4.y * is2)));
    o.z = l4.z * (0.5f * p4.z * (1.0f + erff(p4.z * is2)));
    o.w = l4.w * (0.5f * p4.w * (1.0f + erff(p4.w * is2)));
    ull ph, pl;
    split4(o, ph, pl);
    reinterpret_cast<ull*>(b0 + (size_t)row * 2048)[t] = ph;
    reinterpret_cast<ull*>(b1 + (size_t)row * 2048)[t] = pl;
}

// ---------------- Attention (flash, p=2 power-softmax) ----------------
#define AW 132
#define SSW 66

extern __shared__ float smf[];

__global__ void __launch_bounds__(256, 1) attn_kernel(
        const float* __restrict__ proj, bf16* __restrict__ bo0, bf16* __restrict__ bo1) {
    float* Qn   = smf;
    float* Kn   = Qn + 64 * AW;
    float* Vn   = Kn + 64 * AW;
    float* Ss   = Vn + 64 * AW;
    float* mrow = Ss + 64 * SSW;
    float* zrow = mrow + 64;
    float* arow = zrow + 64;

    int t = threadIdx.x, tx = t & 15, ty = t >> 4;
    int bh = blockIdx.y;
    int b = bh >> 3, h = bh & 7;
    int q0 = blockIdx.x * 64;
    const float* base = proj + (size_t)b * LSEQ * NPROJ + (size_t)h * HD;
    const float scale = 0.08838834764831845f;

    #pragma unroll
    for (int l = 0; l < 8; l++) {
        int idx = t + l * 256;
        int i = idx >> 5, dg = (idx & 31) * 4;
        float4 v = *reinterpret_cast<const float4*>(base + (size_t)(q0 + i) * NPROJ + dg);
        *reinterpret_cast<float4*>(&Qn[i * AW + dg]) = v;
    }
    if (t < 64) { mrow[t] = -1e30f; zrow[t] = 0.f; }

    ull u2[4][4];
    #pragma unroll
    for (int i = 0; i < 4; i++)
        #pragma unroll
        for (int j = 0; j < 4; j++) u2[i][j] = 0ull;

    for (int k0 = 0; k0 < q0 + 64; k0 += 64) {
        __syncthreads();
        #pragma unroll
        for (int l = 0; l < 8; l++) {
            int idx = t + l * 256;
            int i = idx >> 5, dg = (idx & 31) * 4;
            const float* kp = base + DIMX + (size_t)(k0 + i) * NPROJ + dg;
            *reinterpret_cast<float4*>(&Kn[i * AW + dg]) = *reinterpret_cast<const float4*>(kp);
            *reinterpret_cast<float4*>(&Vn[i * AW + dg]) = *reinterpret_cast<const float4*>(kp + DIMX);
        }
        __syncthreads();

        ull s2[4][4];
        #pragma unroll
        for (int i = 0; i < 4; i++)
            #pragma unroll
            for (int j = 0; j < 4; j++) s2[i][j] = 0ull;
        #pragma unroll 4
        for (int d = 0; d < HD; d += 4) {
            ulonglong2 qa[4], kb[4];
            #pragma unroll
            for (int i = 0; i < 4; i++)
                qa[i] = *reinterpret_cast<const ulonglong2*>(&Qn[(ty + 16 * i) * AW + d]);
            #pragma unroll
            for (int j = 0; j < 4; j++)
                kb[j] = *reinterpret_cast<const ulonglong2*>(&Kn[(tx + 16 * j) * AW + d]);
            #pragma unroll
            for (int i = 0; i < 4; i++)
                #pragma unroll
                for (int j = 0; j < 4; j++) {
                    fma2(s2[i][j], qa[i].x, kb[j].x);
                    fma2(s2[i][j], qa[i].y, kb[j].y);
                }
        }
        #pragma unroll
        for (int i = 0; i < 4; i++) {
            int qg = q0 + ty + 16 * i;
            #pragma unroll
            for (int j = 0; j < 4; j++) {
                float e, o_;
                up2(s2[i][j], e, o_);
                float s = (e + o_) * scale;
                int kg = k0 + tx + 16 * j;
                if (kg > qg) s = -1e30f;
                Ss[(ty + 16 * i) * SSW + (tx + 16 * j)] = s;
            }
        }
        __syncthreads();

        if (t < 64) {
            float mo = mrow[t], mn = mo;
            float* srow = &Ss[t * SSW];
            #pragma unroll 8
            for (int c = 0; c < 64; c++) mn = fmaxf(mn, srow[c]);
            float zc = zrow[t] * expf(2.0f * (mo - mn));
            #pragma unroll 8
            for (int c = 0; c < 64; c++) {
                float e = expf(srow[c] - mn);
                srow[c] = e;
                zc += e * e;
            }
            arow[t] = expf(mo - mn);
            mrow[t] = mn;
            zrow[t] = zc;
        }
        __syncthreads();

        #pragma unroll
        for (int i = 0; i < 4; i++) {
            float al = arow[ty + 16 * i];
            ull al2 = pk2(al, al);
            #pragma unroll
            for (int j = 0; j < 4; j++) u2[i][j] = mul2(u2[i][j], al2);
        }
        #pragma unroll 4
        for (int kk = 0; kk < 64; kk++) {
            float p[4];
            #pragma unroll
            for (int i = 0; i < 4; i++) p[i] = Ss[(ty + 16 * i) * SSW + kk];
            ulonglong2 v0 = *reinterpret_cast<const ulonglong2*>(&Vn[kk * AW + tx * 4]);
            ulonglong2 v1 = *reinterpret_cast<const ulonglong2*>(&Vn[kk * AW + tx * 4 + 64]);
            ull vv[4] = {v0.x, v0.y, v1.x, v1.y};
            #pragma unroll
            for (int i = 0; i < 4; i++) {
                ull p2 = pk2(p[i], p[i]);
                fma2(u2[i][0], p2, vv[0]);
                fma2(u2[i][1], p2, vv[1]);
                fma2(u2[i][2], p2, vv[2]);
                fma2(u2[i][3], p2, vv[3]);
            }
        }
    }

    #pragma unroll
    for (int i = 0; i < 4; i++) {
        int qg = q0 + ty + 16 * i;
        float rz = rsqrtf(zrow[ty + 16 * i]);
        size_t ob = (size_t)(b * LSEQ + qg) * 2048 + 1024 + h * HD;
        #pragma unroll
        for (int half = 0; half < 2; half++) {
            float4 o;
            up2(u2[i][half * 2 + 0], o.x, o.y);
            up2(u2[i][half * 2 + 1], o.z, o.w);
            o.x *= rz; o.y *= rz; o.z *= rz; o.w *= rz;
            ull ph, pl;
            split4(o, ph, pl);
            size_t off = ob + tx * 4 + half * 64;
            *reinterpret_cast<ull*>(bo0 + off) = ph;
            *reinterpret_cast<ull*>(bo1 + off) = pl;
        }
    }
}

// ---------------- launch ----------------
extern "C" void kernel_launch(void* const* d_in, const int* in_sizes, int n_in,
                              void* d_out, int out_size) {
    (void)in_sizes; (void)n_in; (void)out_size;
    const float* x     = (const float*)d_in[0];
    const float* gamma = (const float*)d_in[1];
    const float* beta  = (const float*)d_in[2];
    const float* w_qkv = (const float*)d_in[3];
    const float* w_out = (const float*)d_in[4];
    float* out = (float*)d_out;

    void *pp, *ph0, *ph1, *pq0, *pq1, *pb0, *pb1, *po0, *po1;
    cudaGetSymbolAddress(&pp,  g_proj);
    cudaGetSymbolAddress(&ph0, g_h0);  cudaGetSymbolAddress(&ph1, g_h1);
    cudaGetSymbolAddress(&pq0, g_wq0); cudaGetSymbolAddress(&pq1, g_wq1);
    cudaGetSymbolAddress(&pb0, g_br0); cudaGetSymbolAddress(&pb1, g_br1);
    cudaGetSymbolAddress(&po0, g_wo0); cudaGetSymbolAddress(&po1, g_wo1);
    float* proj = (float*)pp;
    bf16 *h0 = (bf16*)ph0, *h1 = (bf16*)ph1;
    bf16 *q0 = (bf16*)pq0, *q1 = (bf16*)pq1;
    bf16 *b0 = (bf16*)pb0, *b1 = (bf16*)pb1;
    bf16 *o0 = (bf16*)po0, *o1 = (bf16*)po1;

    // weight split prepass (bf16 hi/lo planes)
    int nq4 = NPROJ * DIMX / 4, no4 = DIMX * 2048 / 4;
    split_kernel<<<(nq4 + 255) / 256, 256>>>(w_qkv, q0, q1, nq4);
    split_kernel<<<(no4 + 255) / 256, 256>>>(w_out, o0, o1, no4);

    // LayerNorm -> h hi/lo
    ln_kernel<<<ROWS, 256>>>(x, gamma, beta, h0, h1);

    // GEMM1: proj = h @ w_qkv^T   (bf16 3-term, fragment-reuse mainloop)
    cudaFuncSetAttribute(gemm_bf16_kernel<false>,
                         cudaFuncAttributeMaxDynamicSharedMemorySize, GEMM_SMEM);
    cudaFuncSetAttribute(gemm_bf16_kernel<true>,
                         cudaFuncAttributeMaxDynamicSharedMemorySize, GEMM_SMEM);
    gemm_bf16_kernel<false><<<dim3(NPROJ / 128, ROWS / 128), 256, GEMM_SMEM>>>(
        h0, h1, q0, q1, proj, nullptr, DIMX, NPROJ);

    // GELU gate -> branch planes cols [0,1024)
    gelu_kernel<<<ROWS, 256>>>(proj, b0, b1);

    // attention -> branch planes cols [1024,2048)
    int asmem = (3 * 64 * AW + 64 * SSW + 3 * 64) * (int)sizeof(float);
    cudaFuncSetAttribute(attn_kernel, cudaFuncAttributeMaxDynamicSharedMemorySize, asmem);
    attn_kernel<<<dim3(LSEQ / 64, 32), 256, asmem>>>(proj, b0, b1);

    // GEMM2: out = x + branch @ w_out^T  (fused residual)
    gemm_bf16_kernel<true><<<dim3(DIMX / 128, ROWS / 128), 256, GEMM_SMEM>>>(
        b0, b1, o0, o1, out, x, 2048, DIMX);
}

// round 16
// speedup vs baseline: 2.3180x; 1.4260x over previous
#include <cuda_runtime.h>
#include <cuda_bf16.h>
#include <math.h>
#include <stdint.h>

#define DIMX 1024
#define NPROJ 5120
#define ROWS 8192
#define LSEQ 2048
#define HD 128

typedef unsigned long long ull;
typedef __nv_bfloat16 bf16;

// ---------------- scratch (device globals: allocation-free) ----------------
__device__ float g_proj[(size_t)ROWS * NPROJ];        // 160 MB fp32
__device__ bf16  g_h0[(size_t)ROWS * DIMX];
__device__ bf16  g_h1[(size_t)ROWS * DIMX];
__device__ bf16  g_wq0[(size_t)NPROJ * DIMX];
__device__ bf16  g_wq1[(size_t)NPROJ * DIMX];
__device__ bf16  g_br0[(size_t)ROWS * 2048];
__device__ bf16  g_br1[(size_t)ROWS * 2048];
__device__ bf16  g_wo0[(size_t)DIMX * 2048];
__device__ bf16  g_wo1[(size_t)DIMX * 2048];
__device__ bf16  g_qkv0[(size_t)ROWS * 3072];         // q/k/v hi plane
__device__ bf16  g_qkv1[(size_t)ROWS * 3072];         // q/k/v lo plane

// ---------------- bf16 split + pack ----------------
__device__ __forceinline__ void bfsplit(float v, bf16& h, bf16& l) {
    h = __float2bfloat16(v);
    l = __float2bfloat16(v - __bfloat162float(h));
}
__device__ __forceinline__ ull bpack4(bf16 a, bf16 b, bf16 c, bf16 d) {
    unsigned lo = ((unsigned)__bfloat16_as_ushort(b) << 16) | __bfloat16_as_ushort(a);
    unsigned hi = ((unsigned)__bfloat16_as_ushort(d) << 16) | __bfloat16_as_ushort(c);
    return ((ull)hi << 32) | lo;
}
__device__ __forceinline__ void split4(float4 v, ull& ph, ull& pl) {
    bf16 hx, lx, hy, ly, hz, lz, hw, lw;
    bfsplit(v.x, hx, lx); bfsplit(v.y, hy, ly);
    bfsplit(v.z, hz, lz); bfsplit(v.w, hw, lw);
    ph = bpack4(hx, hy, hz, hw);
    pl = bpack4(lx, ly, lz, lw);
}
__device__ __forceinline__ uint32_t pkbf(float lo, float hi) {
    uint32_t r;
    asm("cvt.rn.bf16x2.f32 %0, %1, %2;" : "=r"(r) : "f"(hi), "f"(lo));
    return r;
}
__device__ __forceinline__ float bfhi(float v) {
    return __bfloat162float(__float2bfloat16(v));
}

__device__ __forceinline__ uint32_t smem_u32(const void* p) {
    uint32_t a;
    asm("{ .reg .u64 t; cvta.to.shared.u64 t, %1; cvt.u32.u64 %0, t; }" : "=r"(a) : "l"(p));
    return a;
}

// ---------------- mma/ldmatrix/cp.async macros (baseline PTX) ----------------
#define LDX4(r0, r1, r2, r3, addr)                                            \
    asm volatile("ldmatrix.sync.aligned.m8n8.x4.shared.b16 {%0,%1,%2,%3}, [%4];" \
        : "=r"(r0), "=r"(r1), "=r"(r2), "=r"(r3) : "r"(addr))
#define LDX2(r0, r1, addr)                                                    \
    asm volatile("ldmatrix.sync.aligned.m8n8.x2.shared.b16 {%0,%1}, [%2];"    \
        : "=r"(r0), "=r"(r1) : "r"(addr))
#define LDX2T(r0, r1, addr)                                                   \
    asm volatile("ldmatrix.sync.aligned.m8n8.x2.trans.shared.b16 {%0,%1}, [%2];" \
        : "=r"(r0), "=r"(r1) : "r"(addr))
#define MMA_BF16(c, a, b0, b1)                                                \
    asm volatile("mma.sync.aligned.m16n8k16.row.col.f32.bf16.bf16.f32 "       \
        "{%0,%1,%2,%3}, {%4,%5,%6,%7}, {%8,%9}, {%0,%1,%2,%3};"               \
        : "+f"((c)[0]), "+f"((c)[1]), "+f"((c)[2]), "+f"((c)[3])              \
        : "r"((a)[0]), "r"((a)[1]), "r"((a)[2]), "r"((a)[3]), "r"(b0), "r"(b1))
#define MMA_BF16R(c, a0, a1, a2, a3, b0, b1)                                  \
    asm volatile("mma.sync.aligned.m16n8k16.row.col.f32.bf16.bf16.f32 "       \
        "{%0,%1,%2,%3}, {%4,%5,%6,%7}, {%8,%9}, {%0,%1,%2,%3};"               \
        : "+f"((c)[0]), "+f"((c)[1]), "+f"((c)[2]), "+f"((c)[3])              \
        : "r"(a0), "r"(a1), "r"(a2), "r"(a3), "r"(b0), "r"(b1))
#define CP16(s, g)                                                            \
    asm volatile("cp.async.ca.shared.global [%0], [%1], 16;" :: "r"(s), "l"(g) : "memory")
#define CP_COMMIT asm volatile("cp.async.commit_group;" ::: "memory")
#define CP_WAIT1 asm volatile("cp.async.wait_group 1;" ::: "memory")
#define CP_WAIT0 asm volatile("cp.async.wait_group 0;" ::: "memory")

// ---------------- weight split prepass ----------------
__global__ void __launch_bounds__(256) split_kernel(const float* __restrict__ src,
                                                    bf16* __restrict__ hi,
                                                    bf16* __restrict__ lo, int n4) {
    int i = blockIdx.x * 256 + threadIdx.x;
    if (i >= n4) return;
    float4 v = reinterpret_cast<const float4*>(src)[i];
    ull ph, pl;
    split4(v, ph, pl);
    reinterpret_cast<ull*>(hi)[i] = ph;
    reinterpret_cast<ull*>(lo)[i] = pl;
}

// ---------------- qkv split: proj cols [0,3072) -> bf16 planes ----------------
__global__ void __launch_bounds__(256) qkv_split_kernel(
        const float* __restrict__ proj, bf16* __restrict__ p0, bf16* __restrict__ p1) {
    size_t i = (size_t)blockIdx.x * 256 + threadIdx.x;   // over ROWS*768 float4s
    if (i >= (size_t)ROWS * 768) return;
    size_t row = i / 768, c4 = i % 768;
    float4 v = *reinterpret_cast<const float4*>(proj + row * NPROJ + c4 * 4);
    ull ph, pl;
    split4(v, ph, pl);
    reinterpret_cast<ull*>(p0)[row * 768 + c4] = ph;
    reinterpret_cast<ull*>(p1)[row * 768 + c4] = pl;
}

// ---------------- LayerNorm (emits bf16 hi/lo planes) ----------------
__global__ void __launch_bounds__(256) ln_kernel(
        const float* __restrict__ x, const float* __restrict__ gamma,
        const float* __restrict__ beta, bf16* __restrict__ h0, bf16* __restrict__ h1) {
    int row = blockIdx.x;
    int t = threadIdx.x;
    float4 a = reinterpret_cast<const float4*>(x + (size_t)row * DIMX)[t];
    float s  = a.x + a.y + a.z + a.w;
    float ss = a.x * a.x + a.y * a.y + a.z * a.z + a.w * a.w;
    #pragma unroll
    for (int o = 16; o > 0; o >>= 1) {
        s  += __shfl_xor_sync(0xffffffffu, s, o);
        ss += __shfl_xor_sync(0xffffffffu, ss, o);
    }
    __shared__ float rs[8], rss[8];
    if ((t & 31) == 0) { rs[t >> 5] = s; rss[t >> 5] = ss; }
    __syncthreads();
    if (t < 32) {
        s  = (t < 8) ? rs[t]  : 0.f;
        ss = (t < 8) ? rss[t] : 0.f;
        #pragma unroll
        for (int o = 4; o > 0; o >>= 1) {
            s  += __shfl_xor_sync(0xffffffffu, s, o);
            ss += __shfl_xor_sync(0xffffffffu, ss, o);
        }
        if (t == 0) { rs[0] = s; rss[0] = ss; }
    }
    __syncthreads();
    float mu   = rs[0] * (1.0f / DIMX);
    float var  = rss[0] * (1.0f / DIMX) - mu * mu;
    float rstd = rsqrtf(var + 1e-5f);
    float4 g  = reinterpret_cast<const float4*>(gamma)[t];
    float4 be = reinterpret_cast<const float4*>(beta)[t];
    float4 o;
    o.x = (a.x - mu) * rstd * g.x + be.x;
    o.y = (a.y - mu) * rstd * g.y + be.y;
    o.z = (a.z - mu) * rstd * g.z + be.z;
    o.w = (a.w - mu) * rstd * g.w + be.w;
    ull ph, pl;
    split4(o, ph, pl);
    reinterpret_cast<ull*>(h0 + (size_t)row * DIMX)[t] = ph;
    reinterpret_cast<ull*>(h1 + (size_t)row * DIMX)[t] = pl;
}

// ---------------- bf16 3-term GEMM, fragment-reuse mainloop (unchanged) ----------------
#define SROW 40
#define PLANE (128 * SROW * 2)
#define GBUF (4 * PLANE)
#define GEMM_SMEM (2 * GBUF)

extern __shared__ char smc[];

template<bool RES>
__global__ void __launch_bounds__(256, 2) gemm_bf16_kernel(
        const bf16* __restrict__ A0, const bf16* __restrict__ A1,
        const bf16* __restrict__ B0, const bf16* __restrict__ B1,
        float* __restrict__ C, const float* __restrict__ resid,
        int K, int Ntot) {
    uint32_t sbase = smem_u32(smc);
    int tid = threadIdx.x;
    int lane = tid & 31, wid = tid >> 5;
    int wm = wid >> 1, wn = wid & 1;
    int row0 = blockIdx.y * 128;
    int col0 = blockIdx.x * 128;

    const int NC = K >> 5;

    int lr = tid >> 1;
    int ls2 = (tid & 1) * 2;
    uint32_t sOff = (uint32_t)(lr * SROW + ls2 * 8) * 2;
    const bf16* gA0 = A0 + (size_t)(row0 + lr) * K + ls2 * 8;
    const bf16* gA1 = A1 + (size_t)(row0 + lr) * K + ls2 * 8;
    const bf16* gB0 = B0 + (size_t)(col0 + lr) * K + ls2 * 8;
    const bf16* gB1 = B1 + (size_t)(col0 + lr) * K + ls2 * 8;

    uint32_t aOff[2][2];
    #pragma unroll
    for (int mi = 0; mi < 2; mi++)
        #pragma unroll
        for (int kk = 0; kk < 2; kk++)
            aOff[mi][kk] = (uint32_t)((wm * 32 + mi * 16 + (lane & 15)) * SROW
                                      + kk * 16 + (lane >> 4) * 8) * 2;
    uint32_t bOff = (uint32_t)((wn * 64 + (lane & 7)) * SROW + ((lane >> 3) & 1) * 8) * 2;

    float acc[2][8][4];
    #pragma unroll
    for (int mi = 0; mi < 2; mi++)
        #pragma unroll
        for (int nb = 0; nb < 8; nb++)
            #pragma unroll
            for (int q = 0; q < 4; q++) acc[mi][nb][q] = 0.f;

    auto load_chunk = [&](int c, int buf) {
        uint32_t bb = sbase + (uint32_t)buf * GBUF;
        int k0 = c << 5;
        const bf16* pa0 = gA0 + k0;
        const bf16* pa1 = gA1 + k0;
        const bf16* pb0 = gB0 + k0;
        const bf16* pb1 = gB1 + k0;
        CP16(bb + 0 * PLANE + sOff, pa0); CP16(bb + 0 * PLANE + sOff + 16, pa0 + 8);
        CP16(bb + 1 * PLANE + sOff, pa1); CP16(bb + 1 * PLANE + sOff + 16, pa1 + 8);
        CP16(bb + 2 * PLANE + sOff, pb0); CP16(bb + 2 * PLANE + sOff + 16, pb0 + 8);
        CP16(bb + 3 * PLANE + sOff, pb1); CP16(bb + 3 * PLANE + sOff + 16, pb1 + 8);
        CP_COMMIT;
    };

    load_chunk(0, 0);

    for (int c = 0; c < NC; c++) {
        int buf = c & 1;
        if (c + 1 < NC) { load_chunk(c + 1, buf ^ 1); CP_WAIT1; }
        else           { CP_WAIT0; }
        __syncthreads();

        uint32_t bb = sbase + (uint32_t)buf * GBUF;
        #pragma unroll
        for (int kk = 0; kk < 2; kk++) {
            uint32_t a0f[2][4], a1f[2][4];
            #pragma unroll
            for (int mi = 0; mi < 2; mi++) {
                LDX4(a0f[mi][0], a0f[mi][1], a0f[mi][2], a0f[mi][3],
                     bb + 0 * PLANE + aOff[mi][kk]);
                LDX4(a1f[mi][0], a1f[mi][1], a1f[mi][2], a1f[mi][3],
                     bb + 1 * PLANE + aOff[mi][kk]);
            }
            #pragma unroll
            for (int nb = 0; nb < 8; nb++) {
                uint32_t badd = bOff + (uint32_t)(nb * 8 * SROW + kk * 16) * 2;
                uint32_t q0, q1, r0, r1;
                LDX2(q0, q1, bb + 2 * PLANE + badd);
                LDX2(r0, r1, bb + 3 * PLANE + badd);
                #pragma unroll
                for (int mi = 0; mi < 2; mi++) {
                    MMA_BF16(acc[mi][nb], a0f[mi], q0, q1);
                    MMA_BF16(acc[mi][nb], a0f[mi], r0, r1);
                    MMA_BF16(acc[mi][nb], a1f[mi], q0, q1);
                }
            }
        }
        __syncthreads();
    }

    int gid = lane >> 2, tg = lane & 3;
    #pragma unroll
    for (int mi = 0; mi < 2; mi++) {
        #pragma unroll
        for (int nb = 0; nb < 8; nb++) {
            int r = row0 + wm * 32 + mi * 16 + gid;
            int col = col0 + wn * 64 + nb * 8 + tg * 2;
            float2 v0 = make_float2(acc[mi][nb][0], acc[mi][nb][1]);
            float2 v1 = make_float2(acc[mi][nb][2], acc[mi][nb][3]);
            if (RES) {
                float2 r0 = *reinterpret_cast<const float2*>(resid + (size_t)r * Ntot + col);
                float2 r1 = *reinterpret_cast<const float2*>(resid + (size_t)(r + 8) * Ntot + col);
                v0.x += r0.x; v0.y += r0.y; v1.x += r1.x; v1.y += r1.y;
            }
            *reinterpret_cast<float2*>(C + (size_t)r * Ntot + col) = v0;
            *reinterpret_cast<float2*>(C + (size_t)(r + 8) * Ntot + col) = v1;
        }
    }
}

// ---------------- GELU gate ----------------
__global__ void __launch_bounds__(256) gelu_kernel(
        const float* __restrict__ proj, bf16* __restrict__ b0, bf16* __restrict__ b1) {
    int row = blockIdx.x;
    int t = threadIdx.x;
    float4 l4 = reinterpret_cast<const float4*>(proj + (size_t)row * NPROJ + 3 * DIMX)[t];
    float4 p4 = reinterpret_cast<const float4*>(proj + (size_t)row * NPROJ + 4 * DIMX)[t];
    const float is2 = 0.7071067811865475f;
    float4 o;
    o.x = l4.x * (0.5f * p4.x * (1.0f + erff(p4.x * is2)));
    o.y = l4.y * (0.5f * p4.y * (1.0f + erff(p4.y * is2)));
    o.z = l4.z * (0.5f * p4.z * (1.0f + erff(p4.z * is2)));
    o.w = l4.w * (0.5f * p4.w * (1.0f + erff(p4.w * is2)));
    ull ph, pl;
    split4(o, ph, pl);
    reinterpret_cast<ull*>(b0 + (size_t)row * 2048)[t] = ph;
    reinterpret_cast<ull*>(b1 + (size_t)row * 2048)[t] = pl;
}

// ---------------- Attention: bf16 3-term mma.sync flash (p=2 softmax) ----------------
// q-tile 128, k-tile 64. 8 warps, each 16 q-rows x full 64 k-cols of S.
// P built in-register from S acc; PV accumulates 16x128 per warp.
#define ATW 136                         // bf16 row stride (272 B, conflict-free)
#define AQ_PLANE (128 * ATW * 2)        // 34816 B
#define AKV_PLANE (64 * ATW * 2)        // 17408 B
#define AKV_STAGE (4 * AKV_PLANE)       // 69632 B (K0,K1,V0,V1)
#define ATTN_SMEM (2 * AQ_PLANE + 2 * AKV_STAGE)   // 208896 B

__global__ void __launch_bounds__(256, 1) attn_mma_kernel(
        const bf16* __restrict__ qkv0, const bf16* __restrict__ qkv1,
        bf16* __restrict__ bo0, bf16* __restrict__ bo1) {
    uint32_t sb = smem_u32(smc);
    int tid = threadIdx.x;
    int lane = tid & 31, wid = tid >> 5;
    int gid = lane >> 2, tg = lane & 3;
    int bh = blockIdx.y;
    int b = bh >> 3, h = bh & 7;
    int qt = (int)gridDim.x - 1 - blockIdx.x;       // heavy tiles first
    int q0 = qt * 128;
    int NT = 2 * qt + 2;
    const int CPT = 3072;
    size_t rowbase = (size_t)b * LSEQ;
    const float scale = 0.08838834764831845f;

    const bf16* Qg0 = qkv0 + (rowbase + q0) * CPT + h * HD;
    const bf16* Qg1 = qkv1 + (rowbase + q0) * CPT + h * HD;
    const bf16* Kg0 = qkv0 + rowbase * CPT + DIMX + h * HD;
    const bf16* Kg1 = qkv1 + rowbase * CPT + DIMX + h * HD;
    const bf16* Vg0 = qkv0 + rowbase * CPT + 2 * DIMX + h * HD;
    const bf16* Vg1 = qkv1 + rowbase * CPT + 2 * DIMX + h * HD;

    uint32_t sQ0 = sb, sQ1 = sb + AQ_PLANE;
    uint32_t sKV = sb + 2 * AQ_PLANE;

    // async-load Q planes (128 rows x 16 chunks of 16B each)
    #pragma unroll
    for (int l = 0; l < 8; l++) {
        int idx = tid + l * 256;
        int row = idx >> 4, ch = idx & 15;
        uint32_t so = (uint32_t)(row * 272 + ch * 16);
        CP16(sQ0 + so, Qg0 + (size_t)row * CPT + ch * 8);
        CP16(sQ1 + so, Qg1 + (size_t)row * CPT + ch * 8);
    }
    // async-load KV tile 0 into stage 0
    {
        #pragma unroll
        for (int l = 0; l < 4; l++) {
            int idx = tid + l * 256;
            int row = idx >> 4, ch = idx & 15;
            uint32_t so = (uint32_t)(row * 272 + ch * 16);
            size_t go = (size_t)row * CPT + ch * 8;
            CP16(sKV + 0 * AKV_PLANE + so, Kg0 + go);
            CP16(sKV + 1 * AKV_PLANE + so, Kg1 + go);
            CP16(sKV + 2 * AKV_PLANE + so, Vg0 + go);
            CP16(sKV + 3 * AKV_PLANE + so, Vg1 + go);
        }
        CP_COMMIT;
    }

    float uacc[16][4];
    #pragma unroll
    for (int nb = 0; nb < 16; nb++)
        #pragma unroll
        for (int q = 0; q < 4; q++) uacc[nb][q] = 0.f;
    float m0 = -1e30f, m1 = -1e30f, z0 = 0.f, z1 = 0.f;

    int qg0 = q0 + wid * 16 + gid;
    int qg1 = qg0 + 8;

    // Q ldmatrix offsets (per kc)
    uint32_t qrowoff = (uint32_t)((wid * 16 + (lane & 15)) * 272) + (uint32_t)((lane >> 4) * 16);

    for (int kt = 0; kt < NT; kt++) {
        int st = kt & 1;
        if (kt + 1 < NT) {
            int kn = kt + 1;
            uint32_t dst = sKV + (uint32_t)(st ^ 1) * AKV_STAGE;
            #pragma unroll
            for (int l = 0; l < 4; l++) {
                int idx = tid + l * 256;
                int row = idx >> 4, ch = idx & 15;
                uint32_t so = (uint32_t)(row * 272 + ch * 16);
                size_t go = (size_t)(kn * 64 + row) * CPT + ch * 8;
                CP16(dst + 0 * AKV_PLANE + so, Kg0 + go);
                CP16(dst + 1 * AKV_PLANE + so, Kg1 + go);
                CP16(dst + 2 * AKV_PLANE + so, Vg0 + go);
                CP16(dst + 3 * AKV_PLANE + so, Vg1 + go);
            }
            CP_COMMIT;
            CP_WAIT1;
        } else {
            CP_WAIT0;
        }
        __syncthreads();

        uint32_t kb0 = sKV + (uint32_t)st * AKV_STAGE;
        uint32_t kb1 = kb0 + AKV_PLANE;
        uint32_t vb0 = kb0 + 2 * AKV_PLANE;
        uint32_t vb1 = kb0 + 3 * AKV_PLANE;

        // ---- S = Q K^T (3-term) ----
        float sacc[8][4];
        #pragma unroll
        for (int nb = 0; nb < 8; nb++)
            #pragma unroll
            for (int q = 0; q < 4; q++) sacc[nb][q] = 0.f;

        #pragma unroll
        for (int kc = 0; kc < 8; kc++) {
            uint32_t qa = qrowoff + (uint32_t)(kc * 32);
            uint32_t a0[4], a1[4];
            LDX4(a0[0], a0[1], a0[2], a0[3], sQ0 + qa);
            LDX4(a1[0], a1[1], a1[2], a1[3], sQ1 + qa);
            #pragma unroll
            for (int nb = 0; nb < 8; nb++) {
                uint32_t kadd = (uint32_t)((nb * 8 + (lane & 7)) * 272
                                           + kc * 32 + ((lane >> 3) & 1) * 16);
                uint32_t kq0, kq1, kr0, kr1;
                LDX2(kq0, kq1, kb0 + kadd);
                LDX2(kr0, kr1, kb1 + kadd);
                MMA_BF16(sacc[nb], a0, kq0, kq1);
                MMA_BF16(sacc[nb], a0, kr0, kr1);
                MMA_BF16(sacc[nb], a1, kq0, kq1);
            }
        }

        // ---- scale + causal mask ----
        int k0 = kt * 64;
        bool dz = (k0 + 63 > q0 + wid * 16);
        #pragma unroll
        for (int nb = 0; nb < 8; nb++) {
            #pragma unroll
            for (int q = 0; q < 4; q++) sacc[nb][q] *= scale;
            if (dz) {
                int kg = k0 + nb * 8 + tg * 2;
                if (kg > qg0)     sacc[nb][0] = -1e30f;
                if (kg + 1 > qg0) sacc[nb][1] = -1e30f;
                if (kg > qg1)     sacc[nb][2] = -1e30f;
                if (kg + 1 > qg1) sacc[nb][3] = -1e30f;
            }
        }

        // ---- online p=2 softmax (warp-local) ----
        float mx0 = -1e30f, mx1 = -1e30f;
        #pragma unroll
        for (int nb = 0; nb < 8; nb++) {
            mx0 = fmaxf(mx0, fmaxf(sacc[nb][0], sacc[nb][1]));
            mx1 = fmaxf(mx1, fmaxf(sacc[nb][2], sacc[nb][3]));
        }
        mx0 = fmaxf(mx0, __shfl_xor_sync(0xffffffffu, mx0, 1));
        mx0 = fmaxf(mx0, __shfl_xor_sync(0xffffffffu, mx0, 2));
        mx1 = fmaxf(mx1, __shfl_xor_sync(0xffffffffu, mx1, 1));
        mx1 = fmaxf(mx1, __shfl_xor_sync(0xffffffffu, mx1, 2));
        float mn0 = fmaxf(m0, mx0), mn1 = fmaxf(m1, mx1);
        float al0 = __expf(m0 - mn0), al1 = __expf(m1 - mn1);

        float za0 = 0.f, za1 = 0.f;
        #pragma unroll
        for (int nb = 0; nb < 8; nb++) {
            float e0 = __expf(sacc[nb][0] - mn0);
            float e1 = __expf(sacc[nb][1] - mn0);
            float e2 = __expf(sacc[nb][2] - mn1);
            float e3 = __expf(sacc[nb][3] - mn1);
            sacc[nb][0] = e0; sacc[nb][1] = e1; sacc[nb][2] = e2; sacc[nb][3] = e3;
            za0 += e0 * e0 + e1 * e1;
            za1 += e2 * e2 + e3 * e3;
        }
        za0 += __shfl_xor_sync(0xffffffffu, za0, 1);
        za0 += __shfl_xor_sync(0xffffffffu, za0, 2);
        za1 += __shfl_xor_sync(0xffffffffu, za1, 1);
        za1 += __shfl_xor_sync(0xffffffffu, za1, 2);
        z0 = z0 * al0 * al0 + za0;
        z1 = z1 * al1 * al1 + za1;
        m0 = mn0; m1 = mn1;

        // ---- rescale U ----
        #pragma unroll
        for (int nb = 0; nb < 16; nb++) {
            uacc[nb][0] *= al0; uacc[nb][1] *= al0;
            uacc[nb][2] *= al1; uacc[nb][3] *= al1;
        }

        // ---- U += P V (3-term; P frags built from sacc) ----
        #pragma unroll
        for (int kc = 0; kc < 4; kc++) {
            float e0 = sacc[2 * kc][0],     e1 = sacc[2 * kc][1];
            float e2 = sacc[2 * kc][2],     e3 = sacc[2 * kc][3];
            float f0 = sacc[2 * kc + 1][0], f1 = sacc[2 * kc + 1][1];
            float f2 = sacc[2 * kc + 1][2], f3 = sacc[2 * kc + 1][3];
            uint32_t ah0 = pkbf(e0, e1), ah1 = pkbf(e2, e3);
            uint32_t ah2 = pkbf(f0, f1), ah3 = pkbf(f2, f3);
            uint32_t al_0 = pkbf(e0 - bfhi(e0), e1 - bfhi(e1));
            uint32_t al_1 = pkbf(e2 - bfhi(e2), e3 - bfhi(e3));
            uint32_t al_2 = pkbf(f0 - bfhi(f0), f1 - bfhi(f1));
            uint32_t al_3 = pkbf(f2 - bfhi(f2), f3 - bfhi(f3));
            uint32_t vrow = (uint32_t)((kc * 16 + (lane & 15)) * 272);
            #pragma unroll
            for (int nb = 0; nb < 16; nb++) {
                uint32_t vadd = vrow + (uint32_t)(nb * 16);
                uint32_t v0a, v0b, v1a, v1b;
                LDX2T(v0a, v0b, vb0 + vadd);
                LDX2T(v1a, v1b, vb1 + vadd);
                MMA_BF16R(uacc[nb], ah0, ah1, ah2, ah3, v0a, v0b);
                MMA_BF16R(uacc[nb], ah0, ah1, ah2, ah3, v1a, v1b);
                MMA_BF16R(uacc[nb], al_0, al_1, al_2, al_3, v0a, v0b);
            }
        }
        __syncthreads();
    }

    // ---- O = U * z^{-1/2}; write bf16 hi/lo planes ----
    float rz0 = rsqrtf(z0), rz1 = rsqrtf(z1);
    size_t r0off = (rowbase + qg0) * 2048 + 1024 + h * HD;
    size_t r1off = r0off + (size_t)8 * 2048;
    #pragma unroll
    for (int nb = 0; nb < 16; nb++) {
        int col = nb * 8 + tg * 2;
        float o0 = uacc[nb][0] * rz0, o1 = uacc[nb][1] * rz0;
        float o2 = uacc[nb][2] * rz1, o3 = uacc[nb][3] * rz1;
        *reinterpret_cast<uint32_t*>(bo0 + r0off + col) = pkbf(o0, o1);
        *reinterpret_cast<uint32_t*>(bo1 + r0off + col) = pkbf(o0 - bfhi(o0), o1 - bfhi(o1));
        *reinterpret_cast<uint32_t*>(bo0 + r1off + col) = pkbf(o2, o3);
        *reinterpret_cast<uint32_t*>(bo1 + r1off + col) = pkbf(o2 - bfhi(o2), o3 - bfhi(o3));
    }
}

// ---------------- launch ----------------
extern "C" void kernel_launch(void* const* d_in, const int* in_sizes, int n_in,
                              void* d_out, int out_size) {
    (void)in_sizes; (void)n_in; (void)out_size;
    const float* x     = (const float*)d_in[0];
    const float* gamma = (const float*)d_in[1];
    const float* beta  = (const float*)d_in[2];
    const float* w_qkv = (const float*)d_in[3];
    const float* w_out = (const float*)d_in[4];
    float* out = (float*)d_out;

    void *pp, *ph0, *ph1, *pq0, *pq1, *pb0, *pb1, *po0, *po1, *pk0, *pk1;
    cudaGetSymbolAddress(&pp,  g_proj);
    cudaGetSymbolAddress(&ph0, g_h0);  cudaGetSymbolAddress(&ph1, g_h1);
    cudaGetSymbolAddress(&pq0, g_wq0); cudaGetSymbolAddress(&pq1, g_wq1);
    cudaGetSymbolAddress(&pb0, g_br0); cudaGetSymbolAddress(&pb1, g_br1);
    cudaGetSymbolAddress(&po0, g_wo0); cudaGetSymbolAddress(&po1, g_wo1);
    cudaGetSymbolAddress(&pk0, g_qkv0); cudaGetSymbolAddress(&pk1, g_qkv1);
    float* proj = (float*)pp;
    bf16 *h0 = (bf16*)ph0, *h1 = (bf16*)ph1;
    bf16 *q0 = (bf16*)pq0, *q1 = (bf16*)pq1;
    bf16 *b0 = (bf16*)pb0, *b1 = (bf16*)pb1;
    bf16 *o0 = (bf16*)po0, *o1 = (bf16*)po1;
    bf16 *kv0 = (bf16*)pk0, *kv1 = (bf16*)pk1;

    int nq4 = NPROJ * DIMX / 4, no4 = DIMX * 2048 / 4;
    split_kernel<<<(nq4 + 255) / 256, 256>>>(w_qkv, q0, q1, nq4);
    split_kernel<<<(no4 + 255) / 256, 256>>>(w_out, o0, o1, no4);

    ln_kernel<<<ROWS, 256>>>(x, gamma, beta, h0, h1);

    cudaFuncSetAttribute(gemm_bf16_kernel<false>,
                         cudaFuncAttributeMaxDynamicSharedMemorySize, GEMM_SMEM);
    cudaFuncSetAttribute(gemm_bf16_kernel<true>,
                         cudaFuncAttributeMaxDynamicSharedMemorySize, GEMM_SMEM);
    gemm_bf16_kernel<false><<<dim3(NPROJ / 128, ROWS / 128), 256, GEMM_SMEM>>>(
        h0, h1, q0, q1, proj, nullptr, DIMX, NPROJ);

    gelu_kernel<<<ROWS, 256>>>(proj, b0, b1);

    // qkv cols [0,3072) -> bf16 planes
    qkv_split_kernel<<<(int)(((size_t)ROWS * 768 + 255) / 256), 256>>>(proj, kv0, kv1);

    cudaFuncSetAttribute(attn_mma_kernel,
                         cudaFuncAttributeMaxDynamicSharedMemorySize, ATTN_SMEM);
    attn_mma_kernel<<<dim3(LSEQ / 128, 32), 256, ATTN_SMEM>>>(kv0, kv1, b0, b1);

    gemm_bf16_kernel<true><<<dim3(DIMX / 128, ROWS / 128), 256, GEMM_SMEM>>>(
        b0, b1, o0, o1, out, x, 2048, DIMX);
}